// round 1
// baseline (speedup 1.0000x reference)
#include <cuda_runtime.h>
#include <cstdint>

// Problem shape (fixed by the dataset):
//   x:      [4, 2048, 4096] f32  -> M = 8192 rows, K = 4096
//   weight: [16384, 4096]   f32  -> N = 16384
//   out:    [4, 2048, 16384] f32
constexpr int K_DIM = 4096;
constexpr int KW    = K_DIM / 32;   // 128 words per row
constexpr int M_DIM = 8192;
constexpr int N_DIM = 16384;

// Scratch bitboards (device globals: no runtime allocation allowed).
__device__ __align__(16) uint32_t g_Xp[(size_t)M_DIM * KW];   // 4 MB
__device__ __align__(16) uint32_t g_Wp[(size_t)N_DIM * KW];   // 8 MB

// ---------------------------------------------------------------------------
// Pack kernels: one thread per input element, one bit per thread via ballot.
// Bit l of word w corresponds to element (w*32 + l) -- identical convention
// for X and W, so xor/popcount is layout-consistent.
// ---------------------------------------------------------------------------
__global__ void pack_x_kernel(const float* __restrict__ x) {
    size_t idx = (size_t)blockIdx.x * blockDim.x + threadIdx.x;
    float v = x[idx];
    unsigned bit = (v >= 0.0f) ? 1u : 0u;
    unsigned word = __ballot_sync(0xFFFFFFFFu, bit);
    if ((threadIdx.x & 31u) == 0u) g_Xp[idx >> 5] = word;
}

__global__ void pack_w_kernel(const float* __restrict__ w,
                              const float* __restrict__ th) {
    size_t idx = (size_t)blockIdx.x * blockDim.x + threadIdx.x;
    int o = (int)(idx >> 12);               // idx / 4096 (K_DIM = 4096)
    float v = w[idx] - th[o];
    unsigned bit = (v >= 0.0f) ? 1u : 0u;
    unsigned word = __ballot_sync(0xFFFFFFFFu, bit);
    if ((threadIdx.x & 31u) == 0u) g_Wp[idx >> 5] = word;
}

// ---------------------------------------------------------------------------
// Binary GEMM: C[m][n] = scale * (K - 2 * popc(Xp[m] ^ Wp[n]))
// Tiling: BM=BN=64, BK=16 words, 256 threads (16x16), 4x4 register tile.
// Smem padded to 17 words/row to break the stride-64 bank conflict.
// ---------------------------------------------------------------------------
constexpr int BM = 64;
constexpr int BN = 64;
constexpr int BK = 16;   // words of 32 bits = 512 K-elements per chunk

__global__ void __launch_bounds__(256)
bgemm_kernel(const float* __restrict__ shift, float* __restrict__ out) {
    __shared__ uint32_t As[BM][BK + 1];
    __shared__ uint32_t Bs[BN][BK + 1];

    const int tid = threadIdx.x;
    const int tx = tid & 15;        // 0..15 -> n sub-tile
    const int ty = tid >> 4;        // 0..15 -> m sub-tile
    const int m0 = blockIdx.y * BM;
    const int n0 = blockIdx.x * BN;

    // global-load assignment: 256 threads each fetch one uint4 (4 words)
    const int lr = tid >> 2;        // row 0..63
    const int lg = tid & 3;         // word-group 0..3

    int acc[4][4];
#pragma unroll
    for (int i = 0; i < 4; i++)
#pragma unroll
        for (int j = 0; j < 4; j++) acc[i][j] = 0;

    for (int kw0 = 0; kw0 < KW; kw0 += BK) {
        uint4 a = *reinterpret_cast<const uint4*>(
            &g_Xp[(size_t)(m0 + lr) * KW + kw0 + lg * 4]);
        uint4 b = *reinterpret_cast<const uint4*>(
            &g_Wp[(size_t)(n0 + lr) * KW + kw0 + lg * 4]);
        As[lr][lg * 4 + 0] = a.x; As[lr][lg * 4 + 1] = a.y;
        As[lr][lg * 4 + 2] = a.z; As[lr][lg * 4 + 3] = a.w;
        Bs[lr][lg * 4 + 0] = b.x; Bs[lr][lg * 4 + 1] = b.y;
        Bs[lr][lg * 4 + 2] = b.z; Bs[lr][lg * 4 + 3] = b.w;
        __syncthreads();

#pragma unroll
        for (int w = 0; w < BK; w++) {
            uint32_t av[4], bv[4];
#pragma unroll
            for (int i = 0; i < 4; i++) av[i] = As[ty * 4 + i][w];
#pragma unroll
            for (int j = 0; j < 4; j++) bv[j] = Bs[tx * 4 + j][w];
#pragma unroll
            for (int i = 0; i < 4; i++)
#pragma unroll
                for (int j = 0; j < 4; j++)
                    acc[i][j] += __popc(av[i] ^ bv[j]);
        }
        __syncthreads();
    }

    // pow2 shift scale: 2^round_half_even(clip(shift, -8, 0))
    const float sp = *shift;
    const float scale = exp2f(rintf(fminf(fmaxf(sp, -8.0f), 0.0f)));

#pragma unroll
    for (int i = 0; i < 4; i++) {
        const size_t row = (size_t)(m0 + ty * 4 + i) * N_DIM;
#pragma unroll
        for (int j = 0; j < 4; j++) {
            const int n = n0 + tx * 4 + j;
            out[row + n] = scale * (float)(K_DIM - 2 * acc[i][j]);
        }
    }
}

// ---------------------------------------------------------------------------
// Launch
// ---------------------------------------------------------------------------
extern "C" void kernel_launch(void* const* d_in, const int* in_sizes, int n_in,
                              void* d_out, int out_size) {
    const float* x     = (const float*)d_in[0];   // 33,554,432
    const float* w     = (const float*)d_in[1];   // 67,108,864
    const float* th    = (const float*)d_in[2];   // 16,384
    const float* shift = (const float*)d_in[3];   // 1
    float* out = (float*)d_out;                   // 134,217,728

    {
        const size_t n = (size_t)M_DIM * K_DIM;
        pack_x_kernel<<<(unsigned)(n / 256), 256>>>(x);
    }
    {
        const size_t n = (size_t)N_DIM * K_DIM;
        pack_w_kernel<<<(unsigned)(n / 256), 256>>>(w, th);
    }
    {
        dim3 grid(N_DIM / BN, M_DIM / BM);   // (256, 128)
        bgemm_kernel<<<grid, 256>>>(shift, out);
    }
    (void)in_sizes; (void)n_in; (void)out_size;
}